// round 7
// baseline (speedup 1.0000x reference)
#include <cuda_runtime.h>
#include <math.h>

#define N_MAX  (128 * 128 * 128)
#define T_MAX  4194304u
#define TPB    256

// Static scratch (no allocations).
__device__ unsigned g_idx[N_MAX];                  // 8 MB  hash index per point
__device__ unsigned g_cntp[T_MAX / 4];             // 4 MB  byte-packed ref counts
__device__ float4   g_aos[(size_t)T_MAX * 4];      // 268 MB AoS records (64B/entry)
__device__ double   g_sum, g_sumsq;
__device__ unsigned g_done;
__device__ float2   g_stats;                       // x = mean, y = (2*far/vs/6)/std

__device__ __forceinline__ unsigned hash_idx(unsigned c0, unsigned c1, unsigned c2,
                                             unsigned tsize) {
    unsigned h = (c0 * 1u) ^ (c1 * 2654435761u) ^ (c2 * 805459861u);
    return h % tsize;
}

__device__ __forceinline__ float sigmoidf_(float x) {
    return 1.0f / (1.0f + expf(-x));
}

// Zero packed counts (4 MB) + accumulators.
__global__ void __launch_bounds__(TPB) k_zero(unsigned tsize) {
    unsigned i = blockIdx.x * TPB + threadIdx.x;
    uint4* c4 = (uint4*)g_cntp;
    if (i < tsize / 16) c4[i] = make_uint4(0u, 0u, 0u, 0u);
    if (i == 0) { g_sum = 0.0; g_sumsq = 0.0; g_done = 0u; }
}

// Hash 4 points/thread; byte-packed histogram (no-return atomics).
__global__ void __launch_bounds__(TPB) k_hash_count(const int* __restrict__ coords,
                                                    int n, unsigned tsize) {
    int i0 = (blockIdx.x * TPB + threadIdx.x) * 4;
    if (i0 + 3 < n) {
        const int4* cp = (const int4*)(coords + (size_t)i0 * 3);
        int4 a = __ldcs(cp + 0);
        int4 b = __ldcs(cp + 1);
        int4 c = __ldcs(cp + 2);
        unsigned i0x = hash_idx((unsigned)a.x, (unsigned)a.y, (unsigned)a.z, tsize);
        unsigned i1x = hash_idx((unsigned)a.w, (unsigned)b.x, (unsigned)b.y, tsize);
        unsigned i2x = hash_idx((unsigned)b.z, (unsigned)b.w, (unsigned)c.x, tsize);
        unsigned i3x = hash_idx((unsigned)c.y, (unsigned)c.z, (unsigned)c.w, tsize);
        *(uint4*)(g_idx + i0) = make_uint4(i0x, i1x, i2x, i3x);
        atomicAdd(&g_cntp[i0x >> 2], 1u << ((i0x & 3u) * 8u));
        atomicAdd(&g_cntp[i1x >> 2], 1u << ((i1x & 3u) * 8u));
        atomicAdd(&g_cntp[i2x >> 2], 1u << ((i2x & 3u) * 8u));
        atomicAdd(&g_cntp[i3x >> 2], 1u << ((i3x & 3u) * 8u));
    } else {
        for (int i = i0; i < n; i++) {
            unsigned c0 = (unsigned)coords[3 * i + 0];
            unsigned c1 = (unsigned)coords[3 * i + 1];
            unsigned c2 = (unsigned)coords[3 * i + 2];
            unsigned idx = hash_idx(c0, c1, c2, tsize);
            g_idx[i] = idx;
            atomicAdd(&g_cntp[idx >> 2], 1u << ((idx & 3u) * 8u));
        }
    }
}

// Streaming SoA->AoS transpose fused with the global stats reduction.
// Last-finished block computes g_stats (no separate kernel).
__global__ void __launch_bounds__(TPB) k_transpose(const float* __restrict__ table,
                                                   const float* __restrict__ far_p,
                                                   const int* __restrict__ vs_p,
                                                   unsigned tsize, int n) {
    unsigned t  = threadIdx.x;
    unsigned e4 = blockIdx.x * TPB + t;          // group of 4 entries
    unsigned e  = e4 * 4;

    float4 v[14];
    #pragma unroll
    for (int r = 0; r < 14; r++)
        v[r] = __ldcs((const float4*)(table + (size_t)r * tsize) + e4);

    unsigned cw = g_cntp[e4];
    unsigned cx = cw & 0xFFu, cy = (cw >> 8) & 0xFFu;
    unsigned cz = (cw >> 16) & 0xFFu, cww = cw >> 24;

    // stats: sum/sumsq of rows 0-2, weighted by count
    float s, ss;
    {
        float f0 = (float)cx, f1 = (float)cy, f2 = (float)cz, f3 = (float)cww;
        s  = f0 * (v[0].x + v[1].x + v[2].x)
           + f1 * (v[0].y + v[1].y + v[2].y)
           + f2 * (v[0].z + v[1].z + v[2].z)
           + f3 * (v[0].w + v[1].w + v[2].w);
        ss = f0 * (v[0].x * v[0].x + v[1].x * v[1].x + v[2].x * v[2].x)
           + f1 * (v[0].y * v[0].y + v[1].y * v[1].y + v[2].y * v[2].y)
           + f2 * (v[0].z * v[0].z + v[1].z * v[1].z + v[2].z * v[2].z)
           + f3 * (v[0].w * v[0].w + v[1].w * v[1].w + v[2].w * v[2].w);
    }

    // AoS records (only referenced entries, ~39%)
    float4* rec = g_aos + (size_t)e * 4;
    if (cx) {
        __stcs(rec + 0,  make_float4(v[0].x, v[1].x, v[2].x,  v[3].x));
        __stcs(rec + 1,  make_float4(v[4].x, v[5].x, v[6].x,  v[7].x));
        __stcs(rec + 2,  make_float4(v[8].x, v[9].x, v[10].x, v[11].x));
        __stcs(rec + 3,  make_float4(v[12].x, v[13].x, 0.0f, 0.0f));
    }
    if (cy) {
        __stcs(rec + 4,  make_float4(v[0].y, v[1].y, v[2].y,  v[3].y));
        __stcs(rec + 5,  make_float4(v[4].y, v[5].y, v[6].y,  v[7].y));
        __stcs(rec + 6,  make_float4(v[8].y, v[9].y, v[10].y, v[11].y));
        __stcs(rec + 7,  make_float4(v[12].y, v[13].y, 0.0f, 0.0f));
    }
    if (cz) {
        __stcs(rec + 8,  make_float4(v[0].z, v[1].z, v[2].z,  v[3].z));
        __stcs(rec + 9,  make_float4(v[4].z, v[5].z, v[6].z,  v[7].z));
        __stcs(rec + 10, make_float4(v[8].z, v[9].z, v[10].z, v[11].z));
        __stcs(rec + 11, make_float4(v[12].z, v[13].z, 0.0f, 0.0f));
    }
    if (cww) {
        __stcs(rec + 12, make_float4(v[0].w, v[1].w, v[2].w,  v[3].w));
        __stcs(rec + 13, make_float4(v[4].w, v[5].w, v[6].w,  v[7].w));
        __stcs(rec + 14, make_float4(v[8].w, v[9].w, v[10].w, v[11].w));
        __stcs(rec + 15, make_float4(v[12].w, v[13].w, 0.0f, 0.0f));
    }

    // block stats reduction -> double atomics
    double ds = (double)s, dss = (double)ss;
    #pragma unroll
    for (int o = 16; o > 0; o >>= 1) {
        ds  += __shfl_down_sync(0xFFFFFFFFu, ds,  o);
        dss += __shfl_down_sync(0xFFFFFFFFu, dss, o);
    }
    __shared__ double sh_s[8], sh_ss[8];
    int lane = t & 31, w = t >> 5;
    if (lane == 0) { sh_s[w] = ds; sh_ss[w] = dss; }
    __syncthreads();
    if (t == 0) {
        double ts = 0.0, tss = 0.0;
        for (int k = 0; k < TPB / 32; k++) { ts += sh_s[k]; tss += sh_ss[k]; }
        atomicAdd(&g_sum, ts);
        atomicAdd(&g_sumsq, tss);
        __threadfence();
        unsigned done = atomicAdd(&g_done, 1u);
        if (done == gridDim.x - 1u) {
            // last block: finalize stats here (no extra kernel)
            double M    = 3.0 * (double)n;
            double mean = g_sum / M;
            double var  = (g_sumsq - g_sum * g_sum / M) / (M - 1.0);  // ddof=1
            float stdv  = (float)sqrt(var);
            float f     = __ldg(far_p);
            float vs    = (float)__ldg(vs_p);
            float a     = 2.0f * f / vs;
            g_stats = make_float2((float)mean, a / (6.0f * stdv));
        }
    }
}

// Main pass: 4-lane cooperative fetch of each point's 64B AoS record
// (1 cache line/point), full per-point math, coalesced staged output stores.
__global__ void __launch_bounds__(TPB) k_main(const int* __restrict__ coords,
                                              const float* __restrict__ cam,
                                              const float* __restrict__ far_p,
                                              const int* __restrict__ vs_p,
                                              float* __restrict__ out,
                                              int n) {
    __shared__ __align__(16) float4 shr[TPB * 4];   // 16 KB records
    __shared__ __align__(16) float  sh_c[TPB * 9];  // cov staging
    __shared__ __align__(16) float  sh_m[TPB * 3];
    __shared__ __align__(16) float  sh_h[TPB * 3];

    int t  = threadIdx.x;
    int p0 = blockIdx.x * TPB;

    // cooperative record fetch: quad of lanes per point, 8 records/warp-instr
    int gid = t >> 2, q = t & 3;
    #pragma unroll
    for (int it = 0; it < 4; it++) {
        int pl = it * 64 + gid;
        int p  = p0 + pl;
        if (p < n) {
            unsigned idx = g_idx[p];
            shr[pl * 4 + q] = __ldg(g_aos + (size_t)idx * 4 + q);
        }
    }
    __syncthreads();

    int i = p0 + t;
    float op = 0.0f;
    if (i < n) {
        float f  = __ldg(far_p);
        float vs = (float)__ldg(vs_p);
        float a  = 2.0f * f / vs;
        float off = -f + f / vs;
        float2 st = g_stats;
        float cm0 = __ldg(cam + 0), cm1 = __ldg(cam + 1), cm2 = __ldg(cam + 2);

        float4 ra = shr[t * 4 + 0];   // dm0 dm1 dm2 q0
        float4 rb = shr[t * 4 + 1];   // q1 q2 q3 s0
        float4 rc = shr[t * 4 + 2];   // s1 s2 h0 h1
        float4 rd = shr[t * 4 + 3];   // h2 od - -

        int c0 = coords[3 * i + 0];
        int c1 = coords[3 * i + 1];
        int c2 = coords[3 * i + 2];

        sh_m[t * 3 + 0] = (ra.x - st.x) * st.y + (float)c0 * a + cm0 + off;
        sh_m[t * 3 + 1] = (ra.y - st.x) * st.y + (float)c1 * a + cm1 + off;
        sh_m[t * 3 + 2] = (ra.z - st.x) * st.y + (float)c2 * a + cm2 + off;

        float q0 = ra.w, q1 = rb.x, q2 = rb.y, q3 = rb.z;
        float rn = rsqrtf(q0 * q0 + q1 * q1 + q2 * q2 + q3 * q3);
        float r = q0 * rn, x = q1 * rn, y = q2 * rn, z = q3 * rn;
        float R00 = 1.0f - 2.0f * (y * y + z * z);
        float R01 = 2.0f * (x * y - r * z);
        float R02 = 2.0f * (x * z + r * y);
        float R10 = 2.0f * (x * y + r * z);
        float R11 = 1.0f - 2.0f * (x * x + z * z);
        float R12 = 2.0f * (y * z - r * x);
        float R20 = 2.0f * (x * z - r * y);
        float R21 = 2.0f * (y * z + r * x);
        float R22 = 1.0f - 2.0f * (x * x + y * y);

        float sc0 = sigmoidf_(rb.w) * a;
        float sc1 = sigmoidf_(rc.x) * a;
        float sc2 = sigmoidf_(rc.y) * a;
        float v0 = sc0 * sc0, v1 = sc1 * sc1, v2 = sc2 * sc2;

        float* pc = sh_c + t * 9;
        float c01 = R00 * R10 * v0 + R01 * R11 * v1 + R02 * R12 * v2;
        float c02 = R00 * R20 * v0 + R01 * R21 * v1 + R02 * R22 * v2;
        float c12 = R10 * R20 * v0 + R11 * R21 * v1 + R12 * R22 * v2;
        pc[0] = R00 * R00 * v0 + R01 * R01 * v1 + R02 * R02 * v2;
        pc[1] = c01; pc[2] = c02;
        pc[3] = c01;
        pc[4] = R10 * R10 * v0 + R11 * R11 * v1 + R12 * R12 * v2;
        pc[5] = c12;
        pc[6] = c02; pc[7] = c12;
        pc[8] = R20 * R20 * v0 + R21 * R21 * v1 + R22 * R22 * v2;

        sh_h[t * 3 + 0] = rc.z;
        sh_h[t * 3 + 1] = rc.w;
        sh_h[t * 3 + 2] = rd.x;

        op = 1.0f / (1.0f + expf(4.0f - rd.y));
    }
    __syncthreads();

    float* means = out;
    float* cov   = out + 3  * (size_t)n;
    float* harm  = out + 12 * (size_t)n;
    float* opac  = out + 15 * (size_t)n;

    int blk = min(TPB, n - p0);
    if (blk == TPB) {
        const float4* sm4 = (const float4*)sh_m;
        const float4* sh4 = (const float4*)sh_h;
        const float4* sc4 = (const float4*)sh_c;
        float4* dm4 = (float4*)(means + (size_t)p0 * 3);
        float4* dh4 = (float4*)(harm  + (size_t)p0 * 3);
        float4* dc4 = (float4*)(cov   + (size_t)p0 * 9);
        for (int k = t; k < TPB * 3 / 4; k += TPB) {
            __stcs(dm4 + k, sm4[k]);
            __stcs(dh4 + k, sh4[k]);
        }
        for (int k = t; k < TPB * 9 / 4; k += TPB)
            __stcs(dc4 + k, sc4[k]);
    } else {
        for (int k = t; k < blk * 3; k += TPB) {
            __stcs(means + (size_t)p0 * 3 + k, sh_m[k]);
            __stcs(harm  + (size_t)p0 * 3 + k, sh_h[k]);
        }
        for (int k = t; k < blk * 9; k += TPB)
            __stcs(cov + (size_t)p0 * 9 + k, sh_c[k]);
    }
    if (i < n) __stcs(opac + i, op);
}

extern "C" void kernel_launch(void* const* d_in, const int* in_sizes, int n_in,
                              void* d_out, int out_size) {
    const int*   coords = (const int*)d_in[0];
    const float* table  = (const float*)d_in[1];
    const float* cam    = (const float*)d_in[2];
    const float* far_p  = (const float*)d_in[3];
    const int*   vs_p   = (const int*)d_in[4];
    float*       out    = (float*)d_out;

    int n = in_sizes[0] / 3;
    unsigned tsize = (unsigned)(in_sizes[1] / 14);   // 4194304 for this problem

    int pblocks = (n + TPB - 1) / TPB;
    int hblocks = (n / 4 + TPB - 1) / TPB;
    int zblocks = (int)((tsize / 16 + TPB - 1) / TPB);
    int tblocks = (int)((tsize / 4 + TPB - 1) / TPB);

    k_zero      <<<zblocks, TPB>>>(tsize);
    k_hash_count<<<hblocks, TPB>>>(coords, n, tsize);
    k_transpose <<<tblocks, TPB>>>(table, far_p, vs_p, tsize, n);
    k_main      <<<pblocks, TPB>>>(coords, cam, far_p, vs_p, out, n);
}

// round 8
// speedup vs baseline: 1.0107x; 1.0107x over previous
#include <cuda_runtime.h>
#include <math.h>

#define N_MAX  (128 * 128 * 128)
#define T_MAX  4194304u
#define TPB    256

// Static scratch (no allocations).
__device__ unsigned g_cntp[T_MAX / 4];             // 4 MB  byte-packed ref counts
__device__ float4   g_aos[(size_t)T_MAX * 4];      // 268 MB AoS records (64B/entry)
__device__ double   g_sum, g_sumsq;
__device__ unsigned g_done;
__device__ float2   g_stats;                       // x = mean, y = (2*far/vs/6)/std

__device__ __forceinline__ unsigned hash_idx(unsigned c0, unsigned c1, unsigned c2,
                                             unsigned tsize) {
    unsigned h = (c0 * 1u) ^ (c1 * 2654435761u) ^ (c2 * 805459861u);
    return h % tsize;
}

__device__ __forceinline__ float sigmoidf_(float x) {
    return 1.0f / (1.0f + expf(-x));
}

// Zero packed counts (4 MB) + accumulators.
__global__ void __launch_bounds__(TPB) k_zero(unsigned tsize) {
    unsigned i = blockIdx.x * TPB + threadIdx.x;
    uint4* c4 = (uint4*)g_cntp;
    if (i < tsize / 16) c4[i] = make_uint4(0u, 0u, 0u, 0u);
    if (i == 0) { g_sum = 0.0; g_sumsq = 0.0; g_done = 0u; }
}

// Hash 4 points/thread; byte-packed histogram (no-return atomics).
__global__ void __launch_bounds__(TPB) k_hash_count(const int* __restrict__ coords,
                                                    int n, unsigned tsize) {
    int i0 = (blockIdx.x * TPB + threadIdx.x) * 4;
    if (i0 + 3 < n) {
        const int4* cp = (const int4*)(coords + (size_t)i0 * 3);
        int4 a = __ldg(cp + 0);
        int4 b = __ldg(cp + 1);
        int4 c = __ldg(cp + 2);
        unsigned i0x = hash_idx((unsigned)a.x, (unsigned)a.y, (unsigned)a.z, tsize);
        unsigned i1x = hash_idx((unsigned)a.w, (unsigned)b.x, (unsigned)b.y, tsize);
        unsigned i2x = hash_idx((unsigned)b.z, (unsigned)b.w, (unsigned)c.x, tsize);
        unsigned i3x = hash_idx((unsigned)c.y, (unsigned)c.z, (unsigned)c.w, tsize);
        atomicAdd(&g_cntp[i0x >> 2], 1u << ((i0x & 3u) * 8u));
        atomicAdd(&g_cntp[i1x >> 2], 1u << ((i1x & 3u) * 8u));
        atomicAdd(&g_cntp[i2x >> 2], 1u << ((i2x & 3u) * 8u));
        atomicAdd(&g_cntp[i3x >> 2], 1u << ((i3x & 3u) * 8u));
    } else {
        for (int i = i0; i < n; i++) {
            unsigned c0 = (unsigned)coords[3 * i + 0];
            unsigned c1 = (unsigned)coords[3 * i + 1];
            unsigned c2 = (unsigned)coords[3 * i + 2];
            unsigned idx = hash_idx(c0, c1, c2, tsize);
            atomicAdd(&g_cntp[idx >> 2], 1u << ((idx & 3u) * 8u));
        }
    }
}

// Streaming SoA->AoS transpose fused with the global stats reduction.
// Quad-by-quad row processing keeps <=4 float4 live (low regs, high occ).
// Last-finished block computes g_stats (no separate kernel).
__global__ void __launch_bounds__(TPB) k_transpose(const float* __restrict__ table,
                                                   const float* __restrict__ far_p,
                                                   const int* __restrict__ vs_p,
                                                   unsigned tsize, int n) {
    unsigned t  = threadIdx.x;
    unsigned e4 = blockIdx.x * TPB + t;          // group of 4 entries
    unsigned e  = e4 * 4;

    unsigned cw = g_cntp[e4];
    bool bx = (cw & 0xFFu)        != 0u;
    bool by = (cw & 0xFF00u)      != 0u;
    bool bz = (cw & 0xFF0000u)    != 0u;
    bool bw = (cw & 0xFF000000u)  != 0u;

    float4* rec = g_aos + (size_t)e * 4;
    float s = 0.0f, ss = 0.0f;

    // quad 0: rows 0-3 (stats from rows 0-2)
    {
        float4 v0 = __ldcs((const float4*)(table + 0 * (size_t)tsize) + e4);
        float4 v1 = __ldcs((const float4*)(table + 1 * (size_t)tsize) + e4);
        float4 v2 = __ldcs((const float4*)(table + 2 * (size_t)tsize) + e4);
        float4 v3 = __ldcs((const float4*)(table + 3 * (size_t)tsize) + e4);
        float f0 = (float)(cw & 0xFFu);
        float f1 = (float)((cw >> 8) & 0xFFu);
        float f2 = (float)((cw >> 16) & 0xFFu);
        float f3 = (float)(cw >> 24);
        s  = f0 * (v0.x + v1.x + v2.x) + f1 * (v0.y + v1.y + v2.y)
           + f2 * (v0.z + v1.z + v2.z) + f3 * (v0.w + v1.w + v2.w);
        ss = f0 * (v0.x * v0.x + v1.x * v1.x + v2.x * v2.x)
           + f1 * (v0.y * v0.y + v1.y * v1.y + v2.y * v2.y)
           + f2 * (v0.z * v0.z + v1.z * v1.z + v2.z * v2.z)
           + f3 * (v0.w * v0.w + v1.w * v1.w + v2.w * v2.w);
        if (bx) __stcs(rec + 0,  make_float4(v0.x, v1.x, v2.x, v3.x));
        if (by) __stcs(rec + 4,  make_float4(v0.y, v1.y, v2.y, v3.y));
        if (bz) __stcs(rec + 8,  make_float4(v0.z, v1.z, v2.z, v3.z));
        if (bw) __stcs(rec + 12, make_float4(v0.w, v1.w, v2.w, v3.w));
    }
    // quad 1: rows 4-7
    {
        float4 v0 = __ldcs((const float4*)(table + 4 * (size_t)tsize) + e4);
        float4 v1 = __ldcs((const float4*)(table + 5 * (size_t)tsize) + e4);
        float4 v2 = __ldcs((const float4*)(table + 6 * (size_t)tsize) + e4);
        float4 v3 = __ldcs((const float4*)(table + 7 * (size_t)tsize) + e4);
        if (bx) __stcs(rec + 1,  make_float4(v0.x, v1.x, v2.x, v3.x));
        if (by) __stcs(rec + 5,  make_float4(v0.y, v1.y, v2.y, v3.y));
        if (bz) __stcs(rec + 9,  make_float4(v0.z, v1.z, v2.z, v3.z));
        if (bw) __stcs(rec + 13, make_float4(v0.w, v1.w, v2.w, v3.w));
    }
    // quad 2: rows 8-11
    {
        float4 v0 = __ldcs((const float4*)(table + 8  * (size_t)tsize) + e4);
        float4 v1 = __ldcs((const float4*)(table + 9  * (size_t)tsize) + e4);
        float4 v2 = __ldcs((const float4*)(table + 10 * (size_t)tsize) + e4);
        float4 v3 = __ldcs((const float4*)(table + 11 * (size_t)tsize) + e4);
        if (bx) __stcs(rec + 2,  make_float4(v0.x, v1.x, v2.x, v3.x));
        if (by) __stcs(rec + 6,  make_float4(v0.y, v1.y, v2.y, v3.y));
        if (bz) __stcs(rec + 10, make_float4(v0.z, v1.z, v2.z, v3.z));
        if (bw) __stcs(rec + 14, make_float4(v0.w, v1.w, v2.w, v3.w));
    }
    // quad 3: rows 12-13
    {
        float4 v0 = __ldcs((const float4*)(table + 12 * (size_t)tsize) + e4);
        float4 v1 = __ldcs((const float4*)(table + 13 * (size_t)tsize) + e4);
        if (bx) __stcs(rec + 3,  make_float4(v0.x, v1.x, 0.0f, 0.0f));
        if (by) __stcs(rec + 7,  make_float4(v0.y, v1.y, 0.0f, 0.0f));
        if (bz) __stcs(rec + 11, make_float4(v0.z, v1.z, 0.0f, 0.0f));
        if (bw) __stcs(rec + 15, make_float4(v0.w, v1.w, 0.0f, 0.0f));
    }

    // block stats reduction -> double atomics
    double ds = (double)s, dss = (double)ss;
    #pragma unroll
    for (int o = 16; o > 0; o >>= 1) {
        ds  += __shfl_down_sync(0xFFFFFFFFu, ds,  o);
        dss += __shfl_down_sync(0xFFFFFFFFu, dss, o);
    }
    __shared__ double sh_s[8], sh_ss[8];
    int lane = t & 31, w = t >> 5;
    if (lane == 0) { sh_s[w] = ds; sh_ss[w] = dss; }
    __syncthreads();
    if (t == 0) {
        double ts = 0.0, tss = 0.0;
        for (int k = 0; k < TPB / 32; k++) { ts += sh_s[k]; tss += sh_ss[k]; }
        atomicAdd(&g_sum, ts);
        atomicAdd(&g_sumsq, tss);
        __threadfence();
        unsigned done = atomicAdd(&g_done, 1u);
        if (done == gridDim.x - 1u) {
            double M    = 3.0 * (double)n;
            double mean = g_sum / M;
            double var  = (g_sumsq - g_sum * g_sum / M) / (M - 1.0);  // ddof=1
            float stdv  = (float)sqrt(var);
            float f     = __ldg(far_p);
            float vs    = (float)__ldg(vs_p);
            float a     = 2.0f * f / vs;
            g_stats = make_float2((float)mean, a / (6.0f * stdv));
        }
    }
}

// Main pass: coords staged to smem (int4 coalesced), hash recomputed in-kernel,
// 4-lane cooperative fetch of each point's 64B record (1 line/point).
// Record smem is reused for output staging (16KB union -> 8 blocks/SM).
__global__ void __launch_bounds__(TPB) k_main(const int* __restrict__ coords,
                                              const float* __restrict__ cam,
                                              const float* __restrict__ far_p,
                                              const int* __restrict__ vs_p,
                                              float* __restrict__ out,
                                              int n, unsigned tsize) {
    __shared__ int sh_co[TPB * 3];                        // 3 KB coords
    __shared__ __align__(16) float smem_u[TPB * 16];      // 16 KB union
    float4* shr  = (float4*)smem_u;          // phase A: records
    float*  sh_m = smem_u;                   // phase B: means  [TPB*3]
    float*  sh_h = smem_u + TPB * 3;         //          harm   [TPB*3]
    float*  sh_c = smem_u + TPB * 6;         //          cov    [TPB*9]

    int t  = threadIdx.x;
    int p0 = blockIdx.x * TPB;
    int blk = min(TPB, n - p0);

    // coords -> smem (coalesced int4 when full block)
    if (blk == TPB) {
        if (t < TPB * 3 / 4)
            ((int4*)sh_co)[t] = __ldg((const int4*)(coords + (size_t)p0 * 3) + t);
    } else {
        for (int k = t; k < blk * 3; k += TPB)
            sh_co[k] = coords[(size_t)p0 * 3 + k];
    }
    __syncthreads();

    // cooperative record fetch: quad of lanes per point; hash recomputed
    int gid = t >> 2, q = t & 3;
    #pragma unroll
    for (int it = 0; it < 4; it++) {
        int pl = it * 64 + gid;
        if (pl < blk) {
            unsigned idx = hash_idx((unsigned)sh_co[pl * 3 + 0],
                                    (unsigned)sh_co[pl * 3 + 1],
                                    (unsigned)sh_co[pl * 3 + 2], tsize);
            shr[pl * 4 + q] = __ldg(g_aos + (size_t)idx * 4 + q);
        }
    }
    __syncthreads();

    // pull own record + coords into registers before smem reuse
    float4 ra, rb, rc, rd;
    int c0 = 0, c1 = 0, c2 = 0;
    if (t < blk) {
        ra = shr[t * 4 + 0];   // dm0 dm1 dm2 q0
        rb = shr[t * 4 + 1];   // q1 q2 q3 s0
        rc = shr[t * 4 + 2];   // s1 s2 h0 h1
        rd = shr[t * 4 + 3];   // h2 od - -
        c0 = sh_co[t * 3 + 0];
        c1 = sh_co[t * 3 + 1];
        c2 = sh_co[t * 3 + 2];
    }
    __syncthreads();

    float op = 0.0f;
    if (t < blk) {
        float f  = __ldg(far_p);
        float vs = (float)__ldg(vs_p);
        float a  = 2.0f * f / vs;
        float off = -f + f / vs;
        float2 st = g_stats;
        float cm0 = __ldg(cam + 0), cm1 = __ldg(cam + 1), cm2 = __ldg(cam + 2);

        sh_m[t * 3 + 0] = (ra.x - st.x) * st.y + (float)c0 * a + cm0 + off;
        sh_m[t * 3 + 1] = (ra.y - st.x) * st.y + (float)c1 * a + cm1 + off;
        sh_m[t * 3 + 2] = (ra.z - st.x) * st.y + (float)c2 * a + cm2 + off;

        float q0 = ra.w, q1 = rb.x, q2 = rb.y, q3 = rb.z;
        float rn = rsqrtf(q0 * q0 + q1 * q1 + q2 * q2 + q3 * q3);
        float r = q0 * rn, x = q1 * rn, y = q2 * rn, z = q3 * rn;
        float R00 = 1.0f - 2.0f * (y * y + z * z);
        float R01 = 2.0f * (x * y - r * z);
        float R02 = 2.0f * (x * z + r * y);
        float R10 = 2.0f * (x * y + r * z);
        float R11 = 1.0f - 2.0f * (x * x + z * z);
        float R12 = 2.0f * (y * z - r * x);
        float R20 = 2.0f * (x * z - r * y);
        float R21 = 2.0f * (y * z + r * x);
        float R22 = 1.0f - 2.0f * (x * x + y * y);

        float sc0 = sigmoidf_(rb.w) * a;
        float sc1 = sigmoidf_(rc.x) * a;
        float sc2 = sigmoidf_(rc.y) * a;
        float v0 = sc0 * sc0, v1 = sc1 * sc1, v2 = sc2 * sc2;

        float* pc = sh_c + t * 9;
        float c01 = R00 * R10 * v0 + R01 * R11 * v1 + R02 * R12 * v2;
        float c02 = R00 * R20 * v0 + R01 * R21 * v1 + R02 * R22 * v2;
        float c12 = R10 * R20 * v0 + R11 * R21 * v1 + R12 * R22 * v2;
        pc[0] = R00 * R00 * v0 + R01 * R01 * v1 + R02 * R02 * v2;
        pc[1] = c01; pc[2] = c02;
        pc[3] = c01;
        pc[4] = R10 * R10 * v0 + R11 * R11 * v1 + R12 * R12 * v2;
        pc[5] = c12;
        pc[6] = c02; pc[7] = c12;
        pc[8] = R20 * R20 * v0 + R21 * R21 * v1 + R22 * R22 * v2;

        sh_h[t * 3 + 0] = rc.z;
        sh_h[t * 3 + 1] = rc.w;
        sh_h[t * 3 + 2] = rd.x;

        op = 1.0f / (1.0f + expf(4.0f - rd.y));
    }
    __syncthreads();

    float* means = out;
    float* cov   = out + 3  * (size_t)n;
    float* harm  = out + 12 * (size_t)n;
    float* opac  = out + 15 * (size_t)n;

    if (blk == TPB) {
        const float4* sm4 = (const float4*)sh_m;
        const float4* sh4 = (const float4*)sh_h;
        const float4* sc4 = (const float4*)sh_c;
        float4* dm4 = (float4*)(means + (size_t)p0 * 3);
        float4* dh4 = (float4*)(harm  + (size_t)p0 * 3);
        float4* dc4 = (float4*)(cov   + (size_t)p0 * 9);
        for (int k = t; k < TPB * 3 / 4; k += TPB) {
            __stcs(dm4 + k, sm4[k]);
            __stcs(dh4 + k, sh4[k]);
        }
        for (int k = t; k < TPB * 9 / 4; k += TPB)
            __stcs(dc4 + k, sc4[k]);
    } else {
        for (int k = t; k < blk * 3; k += TPB) {
            __stcs(means + (size_t)p0 * 3 + k, sh_m[k]);
            __stcs(harm  + (size_t)p0 * 3 + k, sh_h[k]);
        }
        for (int k = t; k < blk * 9; k += TPB)
            __stcs(cov + (size_t)p0 * 9 + k, sh_c[k]);
    }
    if (t < blk) __stcs(opac + p0 + t, op);
}

extern "C" void kernel_launch(void* const* d_in, const int* in_sizes, int n_in,
                              void* d_out, int out_size) {
    const int*   coords = (const int*)d_in[0];
    const float* table  = (const float*)d_in[1];
    const float* cam    = (const float*)d_in[2];
    const float* far_p  = (const float*)d_in[3];
    const int*   vs_p   = (const int*)d_in[4];
    float*       out    = (float*)d_out;

    int n = in_sizes[0] / 3;
    unsigned tsize = (unsigned)(in_sizes[1] / 14);   // 4194304 for this problem

    int pblocks = (n + TPB - 1) / TPB;
    int hblocks = (n / 4 + TPB - 1) / TPB;
    int zblocks = (int)((tsize / 16 + TPB - 1) / TPB);
    int tblocks = (int)((tsize / 4 + TPB - 1) / TPB);

    k_zero      <<<zblocks, TPB>>>(tsize);
    k_hash_count<<<hblocks, TPB>>>(coords, n, tsize);
    k_transpose <<<tblocks, TPB>>>(table, far_p, vs_p, tsize, n);
    k_main      <<<pblocks, TPB>>>(coords, cam, far_p, vs_p, out, n, tsize);
}

// round 9
// speedup vs baseline: 1.0636x; 1.0524x over previous
#include <cuda_runtime.h>
#include <math.h>

#define N_MAX  (128 * 128 * 128)
#define T_MAX  4194304u
#define TPB    256

// Static scratch (no allocations).
__device__ unsigned g_cntp[T_MAX / 4];             // 4 MB  byte-packed ref counts
__device__ float4   g_aos[(size_t)T_MAX * 4];      // 268 MB AoS records (64B/entry)
__device__ double   g_sum, g_sumsq;
__device__ unsigned g_done;
__device__ float2   g_stats;                       // x = mean, y = (2*far/vs/6)/std

__device__ __forceinline__ unsigned hash_idx(unsigned c0, unsigned c1, unsigned c2,
                                             unsigned tsize) {
    unsigned h = (c0 * 1u) ^ (c1 * 2654435761u) ^ (c2 * 805459861u);
    return h % tsize;
}

__device__ __forceinline__ float sigmoidf_(float x) {
    return 1.0f / (1.0f + expf(-x));
}

// Zero packed counts (4 MB) + accumulators.
__global__ void __launch_bounds__(TPB) k_zero(unsigned tsize) {
    unsigned i = blockIdx.x * TPB + threadIdx.x;
    uint4* c4 = (uint4*)g_cntp;
    if (i < tsize / 16) c4[i] = make_uint4(0u, 0u, 0u, 0u);
    if (i == 0) { g_sum = 0.0; g_sumsq = 0.0; g_done = 0u; }
}

// Hash 4 points/thread; byte-packed histogram (no-return atomics).
__global__ void __launch_bounds__(TPB) k_hash_count(const int* __restrict__ coords,
                                                    int n, unsigned tsize) {
    int i0 = (blockIdx.x * TPB + threadIdx.x) * 4;
    if (i0 + 3 < n) {
        const int4* cp = (const int4*)(coords + (size_t)i0 * 3);
        int4 a = __ldg(cp + 0);
        int4 b = __ldg(cp + 1);
        int4 c = __ldg(cp + 2);
        unsigned i0x = hash_idx((unsigned)a.x, (unsigned)a.y, (unsigned)a.z, tsize);
        unsigned i1x = hash_idx((unsigned)a.w, (unsigned)b.x, (unsigned)b.y, tsize);
        unsigned i2x = hash_idx((unsigned)b.z, (unsigned)b.w, (unsigned)c.x, tsize);
        unsigned i3x = hash_idx((unsigned)c.y, (unsigned)c.z, (unsigned)c.w, tsize);
        atomicAdd(&g_cntp[i0x >> 2], 1u << ((i0x & 3u) * 8u));
        atomicAdd(&g_cntp[i1x >> 2], 1u << ((i1x & 3u) * 8u));
        atomicAdd(&g_cntp[i2x >> 2], 1u << ((i2x & 3u) * 8u));
        atomicAdd(&g_cntp[i3x >> 2], 1u << ((i3x & 3u) * 8u));
    } else {
        for (int i = i0; i < n; i++) {
            unsigned c0 = (unsigned)coords[3 * i + 0];
            unsigned c1 = (unsigned)coords[3 * i + 1];
            unsigned c2 = (unsigned)coords[3 * i + 2];
            unsigned idx = hash_idx(c0, c1, c2, tsize);
            atomicAdd(&g_cntp[idx >> 2], 1u << ((idx & 3u) * 8u));
        }
    }
}

// Streaming SoA->AoS transpose fused with the global stats reduction.
// Quad-by-quad row processing keeps <=4 float4 live (low regs, high occ).
// Last-finished block computes g_stats (no separate kernel).
__global__ void __launch_bounds__(TPB) k_transpose(const float* __restrict__ table,
                                                   const float* __restrict__ far_p,
                                                   const int* __restrict__ vs_p,
                                                   unsigned tsize, int n) {
    unsigned t  = threadIdx.x;
    unsigned e4 = blockIdx.x * TPB + t;          // group of 4 entries
    unsigned e  = e4 * 4;

    unsigned cw = g_cntp[e4];
    bool bx = (cw & 0xFFu)        != 0u;
    bool by = (cw & 0xFF00u)      != 0u;
    bool bz = (cw & 0xFF0000u)    != 0u;
    bool bw = (cw & 0xFF000000u)  != 0u;

    float4* rec = g_aos + (size_t)e * 4;
    float s = 0.0f, ss = 0.0f;

    // quad 0: rows 0-3 (stats from rows 0-2)
    {
        float4 v0 = __ldcs((const float4*)(table + 0 * (size_t)tsize) + e4);
        float4 v1 = __ldcs((const float4*)(table + 1 * (size_t)tsize) + e4);
        float4 v2 = __ldcs((const float4*)(table + 2 * (size_t)tsize) + e4);
        float4 v3 = __ldcs((const float4*)(table + 3 * (size_t)tsize) + e4);
        float f0 = (float)(cw & 0xFFu);
        float f1 = (float)((cw >> 8) & 0xFFu);
        float f2 = (float)((cw >> 16) & 0xFFu);
        float f3 = (float)(cw >> 24);
        s  = f0 * (v0.x + v1.x + v2.x) + f1 * (v0.y + v1.y + v2.y)
           + f2 * (v0.z + v1.z + v2.z) + f3 * (v0.w + v1.w + v2.w);
        ss = f0 * (v0.x * v0.x + v1.x * v1.x + v2.x * v2.x)
           + f1 * (v0.y * v0.y + v1.y * v1.y + v2.y * v2.y)
           + f2 * (v0.z * v0.z + v1.z * v1.z + v2.z * v2.z)
           + f3 * (v0.w * v0.w + v1.w * v1.w + v2.w * v2.w);
        if (bx) __stcs(rec + 0,  make_float4(v0.x, v1.x, v2.x, v3.x));
        if (by) __stcs(rec + 4,  make_float4(v0.y, v1.y, v2.y, v3.y));
        if (bz) __stcs(rec + 8,  make_float4(v0.z, v1.z, v2.z, v3.z));
        if (bw) __stcs(rec + 12, make_float4(v0.w, v1.w, v2.w, v3.w));
    }
    // quad 1: rows 4-7
    {
        float4 v0 = __ldcs((const float4*)(table + 4 * (size_t)tsize) + e4);
        float4 v1 = __ldcs((const float4*)(table + 5 * (size_t)tsize) + e4);
        float4 v2 = __ldcs((const float4*)(table + 6 * (size_t)tsize) + e4);
        float4 v3 = __ldcs((const float4*)(table + 7 * (size_t)tsize) + e4);
        if (bx) __stcs(rec + 1,  make_float4(v0.x, v1.x, v2.x, v3.x));
        if (by) __stcs(rec + 5,  make_float4(v0.y, v1.y, v2.y, v3.y));
        if (bz) __stcs(rec + 9,  make_float4(v0.z, v1.z, v2.z, v3.z));
        if (bw) __stcs(rec + 13, make_float4(v0.w, v1.w, v2.w, v3.w));
    }
    // quad 2: rows 8-11
    {
        float4 v0 = __ldcs((const float4*)(table + 8  * (size_t)tsize) + e4);
        float4 v1 = __ldcs((const float4*)(table + 9  * (size_t)tsize) + e4);
        float4 v2 = __ldcs((const float4*)(table + 10 * (size_t)tsize) + e4);
        float4 v3 = __ldcs((const float4*)(table + 11 * (size_t)tsize) + e4);
        if (bx) __stcs(rec + 2,  make_float4(v0.x, v1.x, v2.x, v3.x));
        if (by) __stcs(rec + 6,  make_float4(v0.y, v1.y, v2.y, v3.y));
        if (bz) __stcs(rec + 10, make_float4(v0.z, v1.z, v2.z, v3.z));
        if (bw) __stcs(rec + 14, make_float4(v0.w, v1.w, v2.w, v3.w));
    }
    // quad 3: rows 12-13
    {
        float4 v0 = __ldcs((const float4*)(table + 12 * (size_t)tsize) + e4);
        float4 v1 = __ldcs((const float4*)(table + 13 * (size_t)tsize) + e4);
        if (bx) __stcs(rec + 3,  make_float4(v0.x, v1.x, 0.0f, 0.0f));
        if (by) __stcs(rec + 7,  make_float4(v0.y, v1.y, 0.0f, 0.0f));
        if (bz) __stcs(rec + 11, make_float4(v0.z, v1.z, 0.0f, 0.0f));
        if (bw) __stcs(rec + 15, make_float4(v0.w, v1.w, 0.0f, 0.0f));
    }

    // block stats reduction -> double atomics
    double ds = (double)s, dss = (double)ss;
    #pragma unroll
    for (int o = 16; o > 0; o >>= 1) {
        ds  += __shfl_down_sync(0xFFFFFFFFu, ds,  o);
        dss += __shfl_down_sync(0xFFFFFFFFu, dss, o);
    }
    __shared__ double sh_s[8], sh_ss[8];
    int lane = t & 31, w = t >> 5;
    if (lane == 0) { sh_s[w] = ds; sh_ss[w] = dss; }
    __syncthreads();
    if (t == 0) {
        double ts = 0.0, tss = 0.0;
        for (int k = 0; k < TPB / 32; k++) { ts += sh_s[k]; tss += sh_ss[k]; }
        atomicAdd(&g_sum, ts);
        atomicAdd(&g_sumsq, tss);
        __threadfence();
        unsigned done = atomicAdd(&g_done, 1u);
        if (done == gridDim.x - 1u) {
            double M    = 3.0 * (double)n;
            double mean = g_sum / M;
            double var  = (g_sumsq - g_sum * g_sum / M) / (M - 1.0);  // ddof=1
            float stdv  = (float)sqrt(var);
            float f     = __ldg(far_p);
            float vs    = (float)__ldg(vs_p);
            float a     = 2.0f * f / vs;
            g_stats = make_float2((float)mean, a / (6.0f * stdv));
        }
    }
}

// Main pass. Each point owns a 20-word smem slot (80B, bank-friendly stride):
//   phase A: 4-lane cooperative fetch of the 64B record into slot words 0-15
//   phase B: thread t consumes slot[t], computes, writes 16 outputs IN PLACE
//            (m0..2 | c00..c22 | h0..2 | op) -- no cross-sync registers
//   phase C: coalesced scalar __stcs stores from strided smem
__global__ void __launch_bounds__(TPB, 8) k_main(const int* __restrict__ coords,
                                                 const float* __restrict__ cam,
                                                 const float* __restrict__ far_p,
                                                 const int* __restrict__ vs_p,
                                                 float* __restrict__ out,
                                                 int n, unsigned tsize) {
    __shared__ int sh_co[TPB * 3];                        // 3 KB coords
    __shared__ __align__(16) float slot[TPB * 20];        // 20 KB slots

    int t  = threadIdx.x;
    int p0 = blockIdx.x * TPB;
    int blk = min(TPB, n - p0);

    // coords -> smem (coalesced int4 when full block)
    if (blk == TPB) {
        if (t < TPB * 3 / 4)
            ((int4*)sh_co)[t] = __ldg((const int4*)(coords + (size_t)p0 * 3) + t);
    } else {
        for (int k = t; k < blk * 3; k += TPB)
            sh_co[k] = coords[(size_t)p0 * 3 + k];
    }
    __syncthreads();

    // phase A: cooperative record fetch (quad of lanes per point)
    int gid = t >> 2, q = t & 3;
    #pragma unroll
    for (int it = 0; it < 4; it++) {
        int pl = it * 64 + gid;
        if (pl < blk) {
            unsigned idx = hash_idx((unsigned)sh_co[pl * 3 + 0],
                                    (unsigned)sh_co[pl * 3 + 1],
                                    (unsigned)sh_co[pl * 3 + 2], tsize);
            *(float4*)(slot + pl * 20 + q * 4) = __ldg(g_aos + (size_t)idx * 4 + q);
        }
    }
    __syncthreads();

    // phase B: per-thread compute, in-place output into own slot
    if (t < blk) {
        float* sl = slot + t * 20;
        float4 ra = *(float4*)(sl + 0);    // dm0 dm1 dm2 q0
        float4 rb = *(float4*)(sl + 4);    // q1 q2 q3 s0
        float4 rc = *(float4*)(sl + 8);    // s1 s2 h0 h1
        float4 rd = *(float4*)(sl + 12);   // h2 od - -

        float f  = __ldg(far_p);
        float vs = (float)__ldg(vs_p);
        float a  = 2.0f * f / vs;
        float off = -f + f / vs;
        float2 st = g_stats;

        int c0 = sh_co[t * 3 + 0];
        int c1 = sh_co[t * 3 + 1];
        int c2 = sh_co[t * 3 + 2];

        sl[0] = (ra.x - st.x) * st.y + (float)c0 * a + __ldg(cam + 0) + off;
        sl[1] = (ra.y - st.x) * st.y + (float)c1 * a + __ldg(cam + 1) + off;
        sl[2] = (ra.z - st.x) * st.y + (float)c2 * a + __ldg(cam + 2) + off;

        float q0 = ra.w, q1 = rb.x, q2 = rb.y, q3 = rb.z;
        float rn = rsqrtf(q0 * q0 + q1 * q1 + q2 * q2 + q3 * q3);
        float r = q0 * rn, x = q1 * rn, y = q2 * rn, z = q3 * rn;
        float R00 = 1.0f - 2.0f * (y * y + z * z);
        float R01 = 2.0f * (x * y - r * z);
        float R02 = 2.0f * (x * z + r * y);
        float R10 = 2.0f * (x * y + r * z);
        float R11 = 1.0f - 2.0f * (x * x + z * z);
        float R12 = 2.0f * (y * z - r * x);
        float R20 = 2.0f * (x * z - r * y);
        float R21 = 2.0f * (y * z + r * x);
        float R22 = 1.0f - 2.0f * (x * x + y * y);

        float sc0 = sigmoidf_(rb.w) * a;
        float sc1 = sigmoidf_(rc.x) * a;
        float sc2 = sigmoidf_(rc.y) * a;
        float v0 = sc0 * sc0, v1 = sc1 * sc1, v2 = sc2 * sc2;

        float c01 = R00 * R10 * v0 + R01 * R11 * v1 + R02 * R12 * v2;
        float c02 = R00 * R20 * v0 + R01 * R21 * v1 + R02 * R22 * v2;
        float c12 = R10 * R20 * v0 + R11 * R21 * v1 + R12 * R22 * v2;
        sl[3]  = R00 * R00 * v0 + R01 * R01 * v1 + R02 * R02 * v2;
        sl[4]  = c01; sl[5] = c02;
        sl[6]  = c01;
        sl[7]  = R10 * R10 * v0 + R11 * R11 * v1 + R12 * R12 * v2;
        sl[8]  = c12;
        sl[9]  = c02; sl[10] = c12;
        sl[11] = R20 * R20 * v0 + R21 * R21 * v1 + R22 * R22 * v2;

        sl[12] = rc.z;
        sl[13] = rc.w;
        sl[14] = rd.x;
        sl[15] = 1.0f / (1.0f + expf(4.0f - rd.y));
    }
    __syncthreads();

    // phase C: coalesced scalar streaming stores
    float* means = out;
    float* cov   = out + 3  * (size_t)n;
    float* harm  = out + 12 * (size_t)n;
    float* opac  = out + 15 * (size_t)n;

    for (int k = t; k < blk * 3; k += TPB)
        __stcs(means + (size_t)p0 * 3 + k, slot[(k / 3) * 20 + (k % 3)]);
    for (int k = t; k < blk * 9; k += TPB)
        __stcs(cov + (size_t)p0 * 9 + k, slot[(k / 9) * 20 + 3 + (k % 9)]);
    for (int k = t; k < blk * 3; k += TPB)
        __stcs(harm + (size_t)p0 * 3 + k, slot[(k / 3) * 20 + 12 + (k % 3)]);
    if (t < blk)
        __stcs(opac + p0 + t, slot[t * 20 + 15]);
}

extern "C" void kernel_launch(void* const* d_in, const int* in_sizes, int n_in,
                              void* d_out, int out_size) {
    const int*   coords = (const int*)d_in[0];
    const float* table  = (const float*)d_in[1];
    const float* cam    = (const float*)d_in[2];
    const float* far_p  = (const float*)d_in[3];
    const int*   vs_p   = (const int*)d_in[4];
    float*       out    = (float*)d_out;

    int n = in_sizes[0] / 3;
    unsigned tsize = (unsigned)(in_sizes[1] / 14);   // 4194304 for this problem

    int pblocks = (n + TPB - 1) / TPB;
    int hblocks = (n / 4 + TPB - 1) / TPB;
    int zblocks = (int)((tsize / 16 + TPB - 1) / TPB);
    int tblocks = (int)((tsize / 4 + TPB - 1) / TPB);

    k_zero      <<<zblocks, TPB>>>(tsize);
    k_hash_count<<<hblocks, TPB>>>(coords, n, tsize);
    k_transpose <<<tblocks, TPB>>>(table, far_p, vs_p, tsize, n);
    k_main      <<<pblocks, TPB>>>(coords, cam, far_p, vs_p, out, n, tsize);
}